// round 2
// baseline (speedup 1.0000x reference)
#include <cuda_runtime.h>
#include <math.h>

#define HDIM   512
#define LWN    32
#define VOCABC 5000
#define NLEAFC 20000
#define NPARC  20000
#define NTOTC  40000
#define MAXLVL 20002
#define MAXCTAS 1024

// ---------------- static device scratch ----------------
__device__ float g_Et[(size_t)VOCABC * HDIM];
__device__ float g_node_h[(size_t)NTOTC * HDIM];
__device__ float g_xe_par[(size_t)NPARC * HDIM];
__device__ float g_Wx[(size_t)NPARC * 3 * HDIM];
__device__ float g_mem[(size_t)NPARC * HDIM];
__device__ float g_zbuf[(size_t)NPARC * HDIM];
__device__ float g_mr[(size_t)NPARC * HDIM];
__device__ int   g_lvl[NTOTC];
__device__ int   g_order[NPARC];
__device__ int   g_lvl_cnt[MAXLVL];
__device__ int   g_lvl_off[MAXLVL + 2];
__device__ int   g_lvl_cur[MAXLVL];
__device__ int   g_maxlvl;
__device__ float g_part[(size_t)MAXCTAS * HDIM];
__device__ unsigned g_bar_cnt;
__device__ unsigned g_bar_gen;

// ---------------- grid barrier (all CTAs co-resident) ----------------
__device__ __forceinline__ void gbar() {
    __syncthreads();
    if (threadIdx.x == 0) {
        __threadfence();
        unsigned gen = *((volatile unsigned*)&g_bar_gen);
        unsigned arr = atomicAdd(&g_bar_cnt, 1u);
        if (arr == gridDim.x - 1) {
            g_bar_cnt = 0;
            __threadfence();
            *((volatile unsigned*)&g_bar_gen) = gen + 1u;
        } else {
            while (*((volatile unsigned*)&g_bar_gen) == gen) { __nanosleep(64); }
            __threadfence();
        }
    }
    __syncthreads();
}

__device__ __forceinline__ float sigm(float x) { return 1.f / (1.f + __expf(-x)); }

// ---------------- tiled fp32 GEMM with fused epilogues ----------------
// C[i,c] = dot(A[row_i, :512], B[c, :512]); B rows picked from B0/B1/B2 per 512-col band.
// mode 0: g_Wx[p*1536+c] = acc + bias(c)
// mode 1: c<512 -> z=sigm(acc+Wx[c]);  c>=512 -> r=sigm(acc+Wx[512+c']); mr = r*mem
// mode 2: cand=tanh(acc+Wx[1024+c]); node_h[L+p] = z*mem + (1-z)*cand
__device__ void run_gemm(int mode, int M, const int* __restrict__ rowids,
                         const float* __restrict__ Asrc, int Nn,
                         const float* __restrict__ B0, const float* __restrict__ B1,
                         const float* __restrict__ B2,
                         const float* __restrict__ bz, const float* __restrict__ br,
                         const float* __restrict__ bh, int L, int cta, int ncta)
{
    __shared__ float As[16][68];
    __shared__ float Bs[16][68];
    __shared__ int   rid[64];
    const int tid = threadIdx.x;
    const int tx = tid & 15, ty = tid >> 4;
    const int li = tid >> 2;
    const int lk = (tid & 3) << 2;
    const int nMt = (M + 63) >> 6, nNt = Nn >> 6;
    const int nTiles = nMt * nNt;

    for (int tile = cta; tile < nTiles; tile += ncta) {
        const int mt = tile / nNt, nt = tile % nNt;
        const int m0 = mt << 6, n0 = nt << 6;
        __syncthreads();
        if (tid < 64) {
            int r = m0 + tid;
            rid[tid] = (r < M) ? (rowids ? rowids[r] : r) : -1;
        }
        __syncthreads();

        const float* Bbase = (n0 < 512) ? B0 : ((n0 < 1024) ? B1 : B2);
        const int nb = n0 & 511;
        const int arow = rid[li];
        const float* aRow = Asrc + (size_t)(arow < 0 ? 0 : arow) * HDIM;
        const float* bRow = Bbase + (size_t)(nb + li) * HDIM;

        float acc[4][4] = {{0.f,0.f,0.f,0.f},{0.f,0.f,0.f,0.f},
                           {0.f,0.f,0.f,0.f},{0.f,0.f,0.f,0.f}};

        for (int k0 = 0; k0 < HDIM; k0 += 16) {
            float4 av = (arow >= 0) ? *(const float4*)(aRow + k0 + lk)
                                    : make_float4(0.f,0.f,0.f,0.f);
            float4 bv = *(const float4*)(bRow + k0 + lk);
            __syncthreads();
            As[lk+0][li] = av.x; As[lk+1][li] = av.y;
            As[lk+2][li] = av.z; As[lk+3][li] = av.w;
            Bs[lk+0][li] = bv.x; Bs[lk+1][li] = bv.y;
            Bs[lk+2][li] = bv.z; Bs[lk+3][li] = bv.w;
            __syncthreads();
#pragma unroll
            for (int kk = 0; kk < 16; kk++) {
                float4 a = *(const float4*)&As[kk][ty << 2];
                float4 b = *(const float4*)&Bs[kk][tx << 2];
                acc[0][0] += a.x*b.x; acc[0][1] += a.x*b.y; acc[0][2] += a.x*b.z; acc[0][3] += a.x*b.w;
                acc[1][0] += a.y*b.x; acc[1][1] += a.y*b.y; acc[1][2] += a.y*b.z; acc[1][3] += a.y*b.w;
                acc[2][0] += a.z*b.x; acc[2][1] += a.z*b.y; acc[2][2] += a.z*b.z; acc[2][3] += a.z*b.w;
                acc[3][0] += a.w*b.x; acc[3][1] += a.w*b.y; acc[3][2] += a.w*b.z; acc[3][3] += a.w*b.w;
            }
        }
#pragma unroll
        for (int ai = 0; ai < 4; ai++) {
            const int p = rid[(ty << 2) + ai];
            if (p < 0) continue;
#pragma unroll
            for (int bi = 0; bi < 4; bi++) {
                const int c = n0 + (tx << 2) + bi;
                const float a = acc[ai][bi];
                if (mode == 0) {
                    float bias = (c < 512) ? bz[c] : ((c < 1024) ? br[c-512] : bh[c-1024]);
                    g_Wx[(size_t)p*1536 + c] = a + bias;
                } else if (mode == 1) {
                    if (c < 512) {
                        g_zbuf[(size_t)p*HDIM + c] = sigm(a + g_Wx[(size_t)p*1536 + c]);
                    } else {
                        const int c2 = c - 512;
                        float r = sigm(a + g_Wx[(size_t)p*1536 + 512 + c2]);
                        g_mr[(size_t)p*HDIM + c2] = r * g_mem[(size_t)p*HDIM + c2];
                    }
                } else {
                    float cc = tanhf(a + g_Wx[(size_t)p*1536 + 1024 + c]);
                    float z  = g_zbuf[(size_t)p*HDIM + c];
                    float mm = g_mem[(size_t)p*HDIM + c];
                    g_node_h[(size_t)(L + p)*HDIM + c] = z*mm + (1.f - z)*cc;
                }
            }
        }
    }
}

// ---------------- 5-layer star attention, one warp per (parent, half) ----------------
__device__ void attn_phase(int off, int B, const int* __restrict__ tree)
{
    const int lane = threadIdx.x & 31;
    const int gw = (blockIdx.x * blockDim.x + threadIdx.x) >> 5;
    const int nw = (gridDim.x * blockDim.x) >> 5;
    for (int item = gw; item < 2 * B; item += nw) {
        const int p = g_order[off + (item >> 1)];
        const int half = item & 1;
        const int cbase = half * 256 + lane * 8;
        float v[4][8];
        unsigned mb = 0u;
#pragma unroll
        for (int i = 0; i < 4; i++) {
            int c = tree[p * 4 + i];
            if (c >= 0) {
                mb |= (1u << i);
                const float4* hp = (const float4*)(g_node_h + (size_t)c*HDIM + cbase);
                float4 a = hp[0], b = hp[1];
                v[i][0]=a.x; v[i][1]=a.y; v[i][2]=a.z; v[i][3]=a.w;
                v[i][4]=b.x; v[i][5]=b.y; v[i][6]=b.z; v[i][7]=b.w;
            } else {
#pragma unroll
                for (int j = 0; j < 8; j++) v[i][j] = 0.f;
            }
        }
        const float denom = (float)max(__popc(mb), 1);
#pragma unroll 1
        for (int layer = 0; layer < 5; layer++) {
            float s[4][4];
#pragma unroll
            for (int i = 0; i < 4; i++)
#pragma unroll
                for (int k = 0; k < 4; k++) {
                    float t = 0.f;
#pragma unroll
                    for (int j = 0; j < 8; j++) t += v[i][j] * v[k][j];
                    t += __shfl_xor_sync(0xffffffffu, t, 1);
                    t += __shfl_xor_sync(0xffffffffu, t, 2);
                    t += __shfl_xor_sync(0xffffffffu, t, 4);
                    s[i][k] = ((mb >> k) & 1u) ? t * 0.125f : -1e9f;
                }
#pragma unroll
            for (int i = 0; i < 4; i++) {
                float mx = fmaxf(fmaxf(s[i][0], s[i][1]), fmaxf(s[i][2], s[i][3]));
                float e0 = __expf(s[i][0]-mx), e1 = __expf(s[i][1]-mx);
                float e2 = __expf(s[i][2]-mx), e3 = __expf(s[i][3]-mx);
                float inv = 1.f / (e0+e1+e2+e3);
                s[i][0]=e0*inv; s[i][1]=e1*inv; s[i][2]=e2*inv; s[i][3]=e3*inv;
            }
            float o[4][8];
#pragma unroll
            for (int i = 0; i < 4; i++)
#pragma unroll
                for (int j = 0; j < 8; j++)
                    o[i][j] = s[i][0]*v[0][j] + s[i][1]*v[1][j]
                            + s[i][2]*v[2][j] + s[i][3]*v[3][j];
#pragma unroll
            for (int i = 0; i < 4; i++)
#pragma unroll
                for (int j = 0; j < 8; j++) v[i][j] = o[i][j];
        }
        float m8[8];
#pragma unroll
        for (int j = 0; j < 8; j++) {
            float t = 0.f;
#pragma unroll
            for (int i = 0; i < 4; i++) if ((mb >> i) & 1u) t += v[i][j];
            m8[j] = t / denom;
        }
        float4* mp = (float4*)(g_mem + (size_t)p*HDIM + cbase);
        mp[0] = make_float4(m8[0], m8[1], m8[2], m8[3]);
        mp[1] = make_float4(m8[4], m8[5], m8[6], m8[7]);
    }
}

// ---------------- the persistent kernel ----------------
extern "C" __global__ void __launch_bounds__(256, 2) star_all(
    const float* __restrict__ xw, const int* __restrict__ xi, const int* __restrict__ tree,
    const float* __restrict__ Ebu,
    const float* __restrict__ Wz, const float* __restrict__ Uz, const float* __restrict__ bz,
    const float* __restrict__ Wr, const float* __restrict__ Ur, const float* __restrict__ br,
    const float* __restrict__ Wh, const float* __restrict__ Uh, const float* __restrict__ bh,
    const float* __restrict__ Wout, const float* __restrict__ bout,
    float* __restrict__ out, int N, int P)
{
    const int L = N - P;
    const int tid = threadIdx.x;
    const int gtid = blockIdx.x * blockDim.x + tid;
    const int nthreads = gridDim.x * blockDim.x;

    // ---- P0: init levels/counters + transpose embedding ----
    for (int n = gtid; n < N; n += nthreads) g_lvl[n] = (n < L) ? 0 : -1;
    for (int i = gtid; i < MAXLVL; i += nthreads) g_lvl_cnt[i] = 0;
    if (gtid == 0) g_maxlvl = 0;
    {
        const int tot = HDIM * VOCABC;
        for (int e = gtid; e < tot; e += nthreads) {
            int h = e / VOCABC, v = e - h * VOCABC;
            g_Et[(size_t)v * HDIM + h] = Ebu[e];
        }
    }
    gbar();

    // ---- P1: embedding xe = sum_l Et[idx]*w ----
    {
        const int c0 = tid, c1 = tid + 256;
        for (int n = blockIdx.x; n < N; n += gridDim.x) {
            float a0 = 0.f, a1 = 0.f;
            const int*   ip = xi + (size_t)n * LWN;
            const float* wp = xw + (size_t)n * LWN;
#pragma unroll 4
            for (int l = 0; l < LWN; l++) {
                const float w = wp[l];
                const float* er = g_Et + (size_t)ip[l] * HDIM;
                a0 += er[c0] * w;
                a1 += er[c1] * w;
            }
            float* dst = (n < L) ? (g_node_h + (size_t)n * HDIM)
                                 : (g_xe_par + (size_t)(n - L) * HDIM);
            dst[c0] = a0; dst[c1] = a1;
        }
    }
    gbar();

    // ---- P2: level discovery (dataflow spin, deps point to lower ids) ----
    for (int p = gtid; p < P; p += nthreads) {
        int lv = 0;
#pragma unroll
        for (int i = 0; i < 4; i++) {
            int c = tree[p * 4 + i];
            if (c >= 0) {
                int cl;
                if (c < L) cl = 0;
                else {
                    while ((cl = *((volatile int*)&g_lvl[c])) < 0) { __nanosleep(32); }
                }
                lv = max(lv, cl);
            }
        }
        lv += 1;
        *((volatile int*)&g_lvl[L + p]) = lv;
        atomicAdd(&g_lvl_cnt[lv], 1);
        atomicMax(&g_maxlvl, lv);
    }
    gbar();

    // ---- P3: Wx GEMM on blocks>0; block0 thread0 does level prefix sum ----
    if (blockIdx.x == 0) {
        if (tid == 0) {
            int ml = g_maxlvl;
            int run = 0;
            for (int lv = 1; lv <= ml; lv++) {
                g_lvl_off[lv] = run;
                g_lvl_cur[lv] = run;
                run += g_lvl_cnt[lv];
            }
            g_lvl_off[ml + 1] = run;
        }
        __syncthreads();
    } else {
        run_gemm(0, P, nullptr, g_xe_par, 1536, Wz, Wr, Wh, bz, br, bh, L,
                 blockIdx.x - 1, gridDim.x - 1);
    }
    gbar();

    // ---- P4: scatter parents into level-ordered array ----
    for (int p = gtid; p < P; p += nthreads) {
        int lv = g_lvl[L + p];
        int slot = atomicAdd(&g_lvl_cur[lv], 1);
        g_order[slot] = p;
    }
    gbar();

    // ---- level loop ----
    const int maxlvl = g_maxlvl;
    for (int lv = 1; lv <= maxlvl; lv++) {
        const int off = g_lvl_off[lv];
        const int cnt = g_lvl_off[lv + 1] - off;
        if (cnt == 0) continue;
        attn_phase(off, cnt, tree);
        gbar();
        run_gemm(1, cnt, g_order + off, g_mem, 1024, Uz, Ur, nullptr,
                 nullptr, nullptr, nullptr, L, blockIdx.x, gridDim.x);
        gbar();
        run_gemm(2, cnt, g_order + off, g_mr, 512, Uh, nullptr, nullptr,
                 nullptr, nullptr, nullptr, L, blockIdx.x, gridDim.x);
        gbar();
    }

    // ---- P5: per-CTA column max over parents ----
    {
        const int rpc = (P + gridDim.x - 1) / gridDim.x;
        const int r0 = blockIdx.x * rpc;
        const int r1 = min(r0 + rpc, P);
        const int c0 = tid, c1 = tid + 256;
        float v0 = -3.4e38f, v1 = -3.4e38f;
        for (int r = r0; r < r1; r++) {
            const float* row = g_node_h + (size_t)(L + r) * HDIM;
            v0 = fmaxf(v0, row[c0]);
            v1 = fmaxf(v1, row[c1]);
        }
        g_part[(size_t)blockIdx.x * HDIM + c0] = v0;
        g_part[(size_t)blockIdx.x * HDIM + c1] = v1;
    }
    gbar();

    // ---- P6: block 0 finishes: reduce, matvec, softmax ----
    if (blockIdx.x == 0) {
        __shared__ float sfinal[HDIM];
        __shared__ float slog[4];
        const int c0 = tid, c1 = tid + 256;
        float v0 = -3.4e38f, v1 = -3.4e38f;
        for (int g = 0; g < (int)gridDim.x; g++) {
            v0 = fmaxf(v0, g_part[(size_t)g * HDIM + c0]);
            v1 = fmaxf(v1, g_part[(size_t)g * HDIM + c1]);
        }
        sfinal[c0] = v0; sfinal[c1] = v1;
        __syncthreads();
        const int w = tid >> 5, lane = tid & 31;
        if (w < 4) {
            float t = 0.f;
#pragma unroll
            for (int j = 0; j < 16; j++) {
                int c = lane * 16 + j;
                t += Wout[w * HDIM + c] * sfinal[c];
            }
#pragma unroll
            for (int d = 16; d > 0; d >>= 1) t += __shfl_xor_sync(0xffffffffu, t, d);
            if (lane == 0) slog[w] = t + bout[w];
        }
        __syncthreads();
        if (tid == 0) {
            float mx = fmaxf(fmaxf(slog[0], slog[1]), fmaxf(slog[2], slog[3]));
            float e0 = __expf(slog[0]-mx), e1 = __expf(slog[1]-mx);
            float e2 = __expf(slog[2]-mx), e3 = __expf(slog[3]-mx);
            float inv = 1.f / (e0+e1+e2+e3);
            out[0] = e0*inv; out[1] = e1*inv; out[2] = e2*inv; out[3] = e3*inv;
        }
    }
}

extern "C" void kernel_launch(void* const* d_in, const int* in_sizes, int n_in,
                              void* d_out, int out_size) {
    const float* xw   = (const float*)d_in[0];
    const int*   xi   = (const int*)  d_in[1];
    const int*   tree = (const int*)  d_in[2];
    const float* Ebu  = (const float*)d_in[3];
    const float* Wz   = (const float*)d_in[4];
    const float* Uz   = (const float*)d_in[5];
    const float* bz   = (const float*)d_in[6];
    const float* Wr   = (const float*)d_in[7];
    const float* Ur   = (const float*)d_in[8];
    const float* br   = (const float*)d_in[9];
    const float* Wh   = (const float*)d_in[10];
    const float* Uh   = (const float*)d_in[11];
    const float* bh   = (const float*)d_in[12];
    const float* Wout = (const float*)d_in[13];
    const float* bout = (const float*)d_in[14];
    float* out = (float*)d_out;

    const int N = in_sizes[0] / LWN;
    const int P = in_sizes[2] / 4;

    int dev = 0;
    cudaGetDevice(&dev);
    int smCount = 148;
    cudaDeviceGetAttribute(&smCount, cudaDevAttrMultiProcessorCount, dev);
    int bpm = 1;
    cudaOccupancyMaxActiveBlocksPerMultiprocessor(&bpm, star_all, 256, 0);
    if (bpm < 1) bpm = 1;
    int grid = smCount * bpm;
    if (grid > MAXCTAS) grid = MAXCTAS;

    star_all<<<grid, 256>>>(xw, xi, tree, Ebu, Wz, Uz, bz, Wr, Ur, br,
                            Wh, Uh, bh, Wout, bout, out, N, P);
}

// round 3
// speedup vs baseline: 1.1123x; 1.1123x over previous
#include <cuda_runtime.h>
#include <math.h>

#define HDIM   512
#define LWN    32
#define VOCABC 5000
#define NLEAFC 20000
#define NPARC  20000
#define NTOTC  40000
#define MAXLVL 20002
#define MAXCTAS 1024

// ---------------- static device scratch ----------------
__device__ float g_Et[(size_t)VOCABC * HDIM];
__device__ float g_node_h[(size_t)NTOTC * HDIM];
__device__ float g_xe_par[(size_t)NPARC * HDIM];
__device__ float g_Wx[(size_t)NPARC * 3 * HDIM];
__device__ float g_mem[(size_t)NPARC * HDIM];
__device__ float g_zbuf[(size_t)NPARC * HDIM];
__device__ float g_mr[(size_t)NPARC * HDIM];
__device__ int   g_lvl[NTOTC];
__device__ int   g_order[NPARC];
__device__ int   g_lvl_cnt[MAXLVL];
__device__ int   g_lvl_off[MAXLVL + 2];
__device__ int   g_lvl_cur[MAXLVL];
__device__ int   g_maxlvl;
__device__ float g_part[(size_t)MAXCTAS * HDIM];
__device__ unsigned g_bar_cnt;
__device__ unsigned g_bar_gen;

// ---------------- grid barrier (all CTAs co-resident) ----------------
__device__ __forceinline__ void gbar() {
    __syncthreads();
    if (threadIdx.x == 0) {
        __threadfence();
        unsigned gen = *((volatile unsigned*)&g_bar_gen);
        unsigned arr = atomicAdd(&g_bar_cnt, 1u);
        if (arr == gridDim.x - 1) {
            g_bar_cnt = 0;
            __threadfence();
            *((volatile unsigned*)&g_bar_gen) = gen + 1u;
        } else {
            while (*((volatile unsigned*)&g_bar_gen) == gen) { __nanosleep(32); }
            __threadfence();
        }
    }
    __syncthreads();
}

__device__ __forceinline__ float sigm(float x) { return 1.f / (1.f + __expf(-x)); }

// packed 2xfp32 FMA (Blackwell FFMA2) — bit-identical to two scalar fmaf
__device__ __forceinline__ void ffma2(float2& d, const float2 a, const float2 b) {
    unsigned long long& dd = reinterpret_cast<unsigned long long&>(d);
    const unsigned long long aa = *reinterpret_cast<const unsigned long long*>(&a);
    const unsigned long long bb = *reinterpret_cast<const unsigned long long*>(&b);
    asm("fma.rn.f32x2 %0, %1, %2, %0;" : "+l"(dd) : "l"(aa), "l"(bb));
}

// ---------------- tiled fp32 GEMM (FFMA2) with fused epilogues ----------------
// C[i,c] = dot(A[row_i, :512], B[c, :512]); B rows picked from B0/B1/B2 per 512-col band.
// mode 0: g_Wx[p*1536+c] = acc + bias(c)
// mode 1: c<512 -> z=sigm(acc+Wx[c]);  c>=512 -> r=sigm(acc+Wx[512+c']); mr = r*mem
// mode 2: cand=tanh(acc+Wx[1024+c]); node_h[L+p] = z*mem + (1-z)*cand
// TM = 128 (micro 8x4) or 64 (micro 4x4), TN = 64, 256 threads.
template<int TM>
__device__ void run_gemm(int mode, int M, const int* __restrict__ rowids,
                         const float* __restrict__ Asrc, int Nn,
                         const float* __restrict__ B0, const float* __restrict__ B1,
                         const float* __restrict__ B2,
                         const float* __restrict__ bz, const float* __restrict__ br,
                         const float* __restrict__ bh, int L, int cta, int ncta)
{
    constexpr int MR = TM / 16;   // rows per thread (8 or 4)
    constexpr int PR = MR / 2;    // row pairs per thread (4 or 2)
    __shared__ float As[16][TM + 4];
    __shared__ float Bs[16][68];
    __shared__ int   rid[TM];
    const int tid = threadIdx.x;
    const int tx = tid & 15, ty = tid >> 4;
    const int li = tid >> 2;            // 0..63
    const int lk = (tid & 3) << 2;      // 0,4,8,12
    const int nMt = (M + TM - 1) / TM, nNt = Nn >> 6;
    const int nTiles = nMt * nNt;

    for (int tile = cta; tile < nTiles; tile += ncta) {
        const int mt = tile / nNt, nt = tile % nNt;
        const int m0 = mt * TM, n0 = nt << 6;
        __syncthreads();
        for (int r = tid; r < TM; r += 256) {
            int rr = m0 + r;
            rid[r] = (rr < M) ? (rowids ? rowids[rr] : rr) : -1;
        }
        __syncthreads();

        const float* Bbase = (n0 < 512) ? B0 : ((n0 < 1024) ? B1 : B2);
        const int nb = n0 & 511;
        const int ar0 = rid[li];
        const int ar1 = (TM == 128) ? rid[li + 64] : -1;
        const float* aRow0 = Asrc + (size_t)(ar0 < 0 ? 0 : ar0) * HDIM;
        const float* aRow1 = Asrc + (size_t)(ar1 < 0 ? 0 : ar1) * HDIM;
        const float* bRow  = Bbase + (size_t)(nb + li) * HDIM;

        float2 acc[PR][4];
#pragma unroll
        for (int i = 0; i < PR; i++)
#pragma unroll
            for (int j = 0; j < 4; j++) acc[i][j] = make_float2(0.f, 0.f);

        for (int k0 = 0; k0 < HDIM; k0 += 16) {
            float4 av0 = (ar0 >= 0) ? *(const float4*)(aRow0 + k0 + lk)
                                    : make_float4(0.f, 0.f, 0.f, 0.f);
            float4 av1 = make_float4(0.f, 0.f, 0.f, 0.f);
            if (TM == 128 && ar1 >= 0) av1 = *(const float4*)(aRow1 + k0 + lk);
            float4 bv = *(const float4*)(bRow + k0 + lk);
            __syncthreads();
            As[lk+0][li] = av0.x; As[lk+1][li] = av0.y;
            As[lk+2][li] = av0.z; As[lk+3][li] = av0.w;
            if (TM == 128) {
                As[lk+0][64+li] = av1.x; As[lk+1][64+li] = av1.y;
                As[lk+2][64+li] = av1.z; As[lk+3][64+li] = av1.w;
            }
            Bs[lk+0][li] = bv.x; Bs[lk+1][li] = bv.y;
            Bs[lk+2][li] = bv.z; Bs[lk+3][li] = bv.w;
            __syncthreads();
#pragma unroll
            for (int kk = 0; kk < 16; kk++) {
                float4 b = *(const float4*)&Bs[kk][tx << 2];
                float2 bb0 = make_float2(b.x, b.x);
                float2 bb1 = make_float2(b.y, b.y);
                float2 bb2 = make_float2(b.z, b.z);
                float2 bb3 = make_float2(b.w, b.w);
                const float2* ap = (const float2*)&As[kk][ty * MR];
#pragma unroll
                for (int pr = 0; pr < PR; pr++) {
                    float2 a2 = ap[pr];
                    ffma2(acc[pr][0], a2, bb0);
                    ffma2(acc[pr][1], a2, bb1);
                    ffma2(acc[pr][2], a2, bb2);
                    ffma2(acc[pr][3], a2, bb3);
                }
            }
        }
        // epilogue
#pragma unroll
        for (int pr = 0; pr < PR; pr++) {
#pragma unroll
            for (int h = 0; h < 2; h++) {
                const int lrow = ty * MR + pr * 2 + h;
                const int p = rid[lrow];
                if (p < 0) continue;
#pragma unroll
                for (int j = 0; j < 4; j++) {
                    const int c = n0 + (tx << 2) + j;
                    const float a = h ? acc[pr][j].y : acc[pr][j].x;
                    if (mode == 0) {
                        float bias = (c < 512) ? bz[c] : ((c < 1024) ? br[c-512] : bh[c-1024]);
                        g_Wx[(size_t)p*1536 + c] = a + bias;
                    } else if (mode == 1) {
                        if (c < 512) {
                            g_zbuf[(size_t)p*HDIM + c] = sigm(a + g_Wx[(size_t)p*1536 + c]);
                        } else {
                            const int c2 = c - 512;
                            float r = sigm(a + g_Wx[(size_t)p*1536 + 512 + c2]);
                            g_mr[(size_t)p*HDIM + c2] = r * g_mem[(size_t)p*HDIM + c2];
                        }
                    } else {
                        float cc = tanhf(a + g_Wx[(size_t)p*1536 + 1024 + c]);
                        float z  = g_zbuf[(size_t)p*HDIM + c];
                        float mm = g_mem[(size_t)p*HDIM + c];
                        g_node_h[(size_t)(L + p)*HDIM + c] = z*mm + (1.f - z)*cc;
                    }
                }
            }
        }
    }
}

// ---------------- 5-layer star attention, one warp per (parent, half) ----------------
__device__ void attn_phase(int off, int B, const int* __restrict__ tree)
{
    const int lane = threadIdx.x & 31;
    const int gw = (blockIdx.x * blockDim.x + threadIdx.x) >> 5;
    const int nw = (gridDim.x * blockDim.x) >> 5;
    for (int item = gw; item < 2 * B; item += nw) {
        const int p = g_order[off + (item >> 1)];
        const int half = item & 1;
        const int cbase = half * 256 + lane * 8;
        float v[4][8];
        unsigned mb = 0u;
#pragma unroll
        for (int i = 0; i < 4; i++) {
            int c = tree[p * 4 + i];
            if (c >= 0) {
                mb |= (1u << i);
                const float4* hp = (const float4*)(g_node_h + (size_t)c*HDIM + cbase);
                float4 a = hp[0], b = hp[1];
                v[i][0]=a.x; v[i][1]=a.y; v[i][2]=a.z; v[i][3]=a.w;
                v[i][4]=b.x; v[i][5]=b.y; v[i][6]=b.z; v[i][7]=b.w;
            } else {
#pragma unroll
                for (int j = 0; j < 8; j++) v[i][j] = 0.f;
            }
        }
        const float denom = (float)max(__popc(mb), 1);
#pragma unroll 1
        for (int layer = 0; layer < 5; layer++) {
            float s[4][4];
#pragma unroll
            for (int i = 0; i < 4; i++)
#pragma unroll
                for (int k = 0; k < 4; k++) {
                    float t = 0.f;
#pragma unroll
                    for (int j = 0; j < 8; j++) t += v[i][j] * v[k][j];
                    t += __shfl_xor_sync(0xffffffffu, t, 1);
                    t += __shfl_xor_sync(0xffffffffu, t, 2);
                    t += __shfl_xor_sync(0xffffffffu, t, 4);
                    s[i][k] = ((mb >> k) & 1u) ? t * 0.125f : -1e9f;
                }
#pragma unroll
            for (int i = 0; i < 4; i++) {
                float mx = fmaxf(fmaxf(s[i][0], s[i][1]), fmaxf(s[i][2], s[i][3]));
                float e0 = __expf(s[i][0]-mx), e1 = __expf(s[i][1]-mx);
                float e2 = __expf(s[i][2]-mx), e3 = __expf(s[i][3]-mx);
                float inv = 1.f / (e0+e1+e2+e3);
                s[i][0]=e0*inv; s[i][1]=e1*inv; s[i][2]=e2*inv; s[i][3]=e3*inv;
            }
            float o[4][8];
#pragma unroll
            for (int i = 0; i < 4; i++)
#pragma unroll
                for (int j = 0; j < 8; j++)
                    o[i][j] = s[i][0]*v[0][j] + s[i][1]*v[1][j]
                            + s[i][2]*v[2][j] + s[i][3]*v[3][j];
#pragma unroll
            for (int i = 0; i < 4; i++)
#pragma unroll
                for (int j = 0; j < 8; j++) v[i][j] = o[i][j];
        }
        float m8[8];
#pragma unroll
        for (int j = 0; j < 8; j++) {
            float t = 0.f;
#pragma unroll
            for (int i = 0; i < 4; i++) if ((mb >> i) & 1u) t += v[i][j];
            m8[j] = t / denom;
        }
        float4* mp = (float4*)(g_mem + (size_t)p*HDIM + cbase);
        mp[0] = make_float4(m8[0], m8[1], m8[2], m8[3]);
        mp[1] = make_float4(m8[4], m8[5], m8[6], m8[7]);
    }
}

// ---------------- the persistent kernel ----------------
extern "C" __global__ void __launch_bounds__(256, 2) star_all(
    const float* __restrict__ xw, const int* __restrict__ xi, const int* __restrict__ tree,
    const float* __restrict__ Ebu,
    const float* __restrict__ Wz, const float* __restrict__ Uz, const float* __restrict__ bz,
    const float* __restrict__ Wr, const float* __restrict__ Ur, const float* __restrict__ br,
    const float* __restrict__ Wh, const float* __restrict__ Uh, const float* __restrict__ bh,
    const float* __restrict__ Wout, const float* __restrict__ bout,
    float* __restrict__ out, int N, int P)
{
    const int L = N - P;
    const int tid = threadIdx.x;
    const int gtid = blockIdx.x * blockDim.x + tid;
    const int nthreads = gridDim.x * blockDim.x;

    // ---- P0: init levels/counters + transpose embedding ----
    for (int n = gtid; n < N; n += nthreads) g_lvl[n] = (n < L) ? 0 : -1;
    for (int i = gtid; i < MAXLVL; i += nthreads) g_lvl_cnt[i] = 0;
    if (gtid == 0) g_maxlvl = 0;
    {
        const int tot = HDIM * VOCABC;
        for (int e = gtid; e < tot; e += nthreads) {
            int h = e / VOCABC, v = e - h * VOCABC;
            g_Et[(size_t)v * HDIM + h] = Ebu[e];
        }
    }
    gbar();

    // ---- P1: embedding xe = sum_l Et[idx]*w ----
    {
        const int c0 = tid, c1 = tid + 256;
        for (int n = blockIdx.x; n < N; n += gridDim.x) {
            float a0 = 0.f, a1 = 0.f;
            const int*   ip = xi + (size_t)n * LWN;
            const float* wp = xw + (size_t)n * LWN;
#pragma unroll 4
            for (int l = 0; l < LWN; l++) {
                const float w = wp[l];
                const float* er = g_Et + (size_t)ip[l] * HDIM;
                a0 += er[c0] * w;
                a1 += er[c1] * w;
            }
            float* dst = (n < L) ? (g_node_h + (size_t)n * HDIM)
                                 : (g_xe_par + (size_t)(n - L) * HDIM);
            dst[c0] = a0; dst[c1] = a1;
        }
    }
    gbar();

    // ---- P2: level discovery (dataflow spin, deps point to lower ids) ----
    for (int p = gtid; p < P; p += nthreads) {
        int lv = 0;
#pragma unroll
        for (int i = 0; i < 4; i++) {
            int c = tree[p * 4 + i];
            if (c >= 0) {
                int cl;
                if (c < L) cl = 0;
                else {
                    while ((cl = *((volatile int*)&g_lvl[c])) < 0) { __nanosleep(32); }
                }
                lv = max(lv, cl);
            }
        }
        lv += 1;
        *((volatile int*)&g_lvl[L + p]) = lv;
        atomicAdd(&g_lvl_cnt[lv], 1);
        atomicMax(&g_maxlvl, lv);
    }
    gbar();

    // ---- P3: Wx GEMM on blocks>0; block0 thread0 does level prefix sum ----
    if (blockIdx.x == 0) {
        if (tid == 0) {
            int ml = g_maxlvl;
            int run = 0;
            for (int lv = 1; lv <= ml; lv++) {
                g_lvl_off[lv] = run;
                g_lvl_cur[lv] = run;
                run += g_lvl_cnt[lv];
            }
            g_lvl_off[ml + 1] = run;
        }
        __syncthreads();
    } else {
        run_gemm<128>(0, P, nullptr, g_xe_par, 1536, Wz, Wr, Wh, bz, br, bh, L,
                      blockIdx.x - 1, gridDim.x - 1);
    }
    gbar();

    // ---- P4: scatter parents into level-ordered array ----
    for (int p = gtid; p < P; p += nthreads) {
        int lv = g_lvl[L + p];
        int slot = atomicAdd(&g_lvl_cur[lv], 1);
        g_order[slot] = p;
    }
    gbar();

    // ---- level loop ----
    const int maxlvl = g_maxlvl;
    for (int lv = 1; lv <= maxlvl; lv++) {
        const int off = g_lvl_off[lv];
        const int cnt = g_lvl_off[lv + 1] - off;
        if (cnt == 0) continue;
        attn_phase(off, cnt, tree);
        gbar();
        if (cnt >= 2048) {
            run_gemm<128>(1, cnt, g_order + off, g_mem, 1024, Uz, Ur, nullptr,
                          nullptr, nullptr, nullptr, L, blockIdx.x, gridDim.x);
            gbar();
            run_gemm<128>(2, cnt, g_order + off, g_mr, 512, Uh, nullptr, nullptr,
                          nullptr, nullptr, nullptr, L, blockIdx.x, gridDim.x);
        } else {
            run_gemm<64>(1, cnt, g_order + off, g_mem, 1024, Uz, Ur, nullptr,
                         nullptr, nullptr, nullptr, L, blockIdx.x, gridDim.x);
            gbar();
            run_gemm<64>(2, cnt, g_order + off, g_mr, 512, Uh, nullptr, nullptr,
                         nullptr, nullptr, nullptr, L, blockIdx.x, gridDim.x);
        }
        gbar();
    }

    // ---- P5: per-CTA column max over parents ----
    {
        const int rpc = (P + gridDim.x - 1) / gridDim.x;
        const int r0 = blockIdx.x * rpc;
        const int r1 = min(r0 + rpc, P);
        const int c0 = tid, c1 = tid + 256;
        float v0 = -3.4e38f, v1 = -3.4e38f;
        for (int r = r0; r < r1; r++) {
            const float* row = g_node_h + (size_t)(L + r) * HDIM;
            v0 = fmaxf(v0, row[c0]);
            v1 = fmaxf(v1, row[c1]);
        }
        g_part[(size_t)blockIdx.x * HDIM + c0] = v0;
        g_part[(size_t)blockIdx.x * HDIM + c1] = v1;
    }
    gbar();

    // ---- P6: block 0 finishes: reduce, matvec, softmax ----
    if (blockIdx.x == 0) {
        __shared__ float sfinal[HDIM];
        __shared__ float slog[4];
        const int c0 = tid, c1 = tid + 256;
        float v0 = -3.4e38f, v1 = -3.4e38f;
        for (int g = 0; g < (int)gridDim.x; g++) {
            v0 = fmaxf(v0, g_part[(size_t)g * HDIM + c0]);
            v1 = fmaxf(v1, g_part[(size_t)g * HDIM + c1]);
        }
        sfinal[c0] = v0; sfinal[c1] = v1;
        __syncthreads();
        const int w = tid >> 5, lane = tid & 31;
        if (w < 4) {
            float t = 0.f;
#pragma unroll
            for (int j = 0; j < 16; j++) {
                int c = lane * 16 + j;
                t += Wout[w * HDIM + c] * sfinal[c];
            }
#pragma unroll
            for (int d = 16; d > 0; d >>= 1) t += __shfl_xor_sync(0xffffffffu, t, d);
            if (lane == 0) slog[w] = t + bout[w];
        }
        __syncthreads();
        if (tid == 0) {
            float mx = fmaxf(fmaxf(slog[0], slog[1]), fmaxf(slog[2], slog[3]));
            float e0 = __expf(slog[0]-mx), e1 = __expf(slog[1]-mx);
            float e2 = __expf(slog[2]-mx), e3 = __expf(slog[3]-mx);
            float inv = 1.f / (e0+e1+e2+e3);
            out[0] = e0*inv; out[1] = e1*inv; out[2] = e2*inv; out[3] = e3*inv;
        }
    }
}

extern "C" void kernel_launch(void* const* d_in, const int* in_sizes, int n_in,
                              void* d_out, int out_size) {
    const float* xw   = (const float*)d_in[0];
    const int*   xi   = (const int*)  d_in[1];
    const int*   tree = (const int*)  d_in[2];
    const float* Ebu  = (const float*)d_in[3];
    const float* Wz   = (const float*)d_in[4];
    const float* Uz   = (const float*)d_in[5];
    const float* bz   = (const float*)d_in[6];
    const float* Wr   = (const float*)d_in[7];
    const float* Ur   = (const float*)d_in[8];
    const float* br   = (const float*)d_in[9];
    const float* Wh   = (const float*)d_in[10];
    const float* Uh   = (const float*)d_in[11];
    const float* bh   = (const float*)d_in[12];
    const float* Wout = (const float*)d_in[13];
    const float* bout = (const float*)d_in[14];
    float* out = (float*)d_out;

    const int N = in_sizes[0] / LWN;
    const int P = in_sizes[2] / 4;

    int dev = 0;
    cudaGetDevice(&dev);
    int smCount = 148;
    cudaDeviceGetAttribute(&smCount, cudaDevAttrMultiProcessorCount, dev);
    int bpm = 1;
    cudaOccupancyMaxActiveBlocksPerMultiprocessor(&bpm, star_all, 256, 0);
    if (bpm < 1) bpm = 1;
    int grid = smCount * bpm;
    if (grid > MAXCTAS) grid = MAXCTAS;

    star_all<<<grid, 256>>>(xw, xi, tree, Ebu, Wz, Uz, bz, Wr, Ur, br,
                            Wh, Uh, bh, Wout, bout, out, N, P);
}